// round 4
// baseline (speedup 1.0000x reference)
#include <cuda_runtime.h>
#include <cstdint>

// ---------------- scratch (no allocation allowed -> __device__ globals) -----
__device__ float g_q[1024 * 128];
__device__ float g_k[1024 * 128];
__device__ float g_v[1024 * 128];
__device__ float g_ctx[1024 * 128];
__device__ float g_att[1024 * 128];
__device__ float g_t1[1024 * 256];
__device__ float g_n1[1024 * 256];

// ---------------- QKV projection: q/k/v = x @ Wqkv^T + b --------------------
// grid 128 (8 rows/block), block 384 (one output column each of q|k|v concat)
__global__ __launch_bounds__(384) void qkv_kernel(const float* __restrict__ x,
                                                  const float* __restrict__ W,
                                                  const float* __restrict__ b) {
    __shared__ float xs[8 * 128];
    int rb = blockIdx.x * 8;
    for (int i = threadIdx.x; i < 1024; i += 384) xs[i] = x[rb * 128 + i];
    __syncthreads();
    int j = threadIdx.x;  // 0..383 -> row of in_proj_w
    const float4* w4 = (const float4*)(W + j * 128);
    const float4* xs4 = (const float4*)xs;
    float acc[8] = {0, 0, 0, 0, 0, 0, 0, 0};
#pragma unroll 8
    for (int i4 = 0; i4 < 32; i4++) {
        float4 w = w4[i4];
#pragma unroll
        for (int r = 0; r < 8; r++) {
            float4 xv = xs4[r * 32 + i4];
            acc[r] += w.x * xv.x + w.y * xv.y + w.z * xv.z + w.w * xv.w;
        }
    }
    float bj = b[j];
    float* dst;
    int col;
    if (j < 128) { dst = g_q; col = j; }
    else if (j < 256) { dst = g_k; col = j - 128; }
    else { dst = g_v; col = j - 256; }
#pragma unroll
    for (int r = 0; r < 8; r++) dst[(rb + r) * 128 + col] = acc[r] + bj;
}

// ---------------- attention (fp32, full matrix needed: attn_w is an output) -
// grid 128 (8 query rows/block), block 256 (8 warps)
// dyn smem: Ps[8*1024] scores/probs, Ks[128*33] K chunk, Qs[8*32]
#define ATTN_SMEM_BYTES ((8 * 1024 + 128 * 33 + 8 * 32) * 4)
__global__ __launch_bounds__(256) void attn_kernel(float* __restrict__ attnw) {
    extern __shared__ float sm[];
    float* Ps = sm;
    float* Ks = sm + 8 * 1024;
    float* Qs = Ks + 128 * 33;
    int tid = threadIdx.x, lane = tid & 31, warp = tid >> 5;
    int qbase = blockIdx.x * 8;

    for (int h = 0; h < 4; h++) {
        {   // load + pre-scale Q tile (256 elems == 256 threads)
            int r = tid >> 5, d = tid & 31;
            Qs[tid] = g_q[(qbase + r) * 128 + h * 32 + d] * 0.17677669529663687f; // 1/sqrt(32)
        }
        for (int kc = 0; kc < 8; kc++) {
            __syncthreads();  // protect Ks (and Ps/Qs at head start)
            for (int i = tid; i < 4096; i += 256) {
                int kk = i >> 5, d = i & 31;
                Ks[kk * 33 + d] = g_k[(kc * 128 + kk) * 128 + h * 32 + d];
            }
            __syncthreads();
            // 2x2 register microtile per thread over (row, key)
            int r0 = (tid >> 6) * 2;
            int k0 = (tid & 63) * 2;
            float s00 = 0, s01 = 0, s10 = 0, s11 = 0;
#pragma unroll
            for (int d = 0; d < 32; d++) {
                float qa = Qs[r0 * 32 + d], qb = Qs[(r0 + 1) * 32 + d];
                float ka = Ks[k0 * 33 + d], kb = Ks[(k0 + 1) * 33 + d];
                s00 += qa * ka; s01 += qa * kb;
                s10 += qb * ka; s11 += qb * kb;
            }
            int cb = kc * 128 + k0;
            Ps[r0 * 1024 + cb] = s00;       Ps[r0 * 1024 + cb + 1] = s01;
            Ps[(r0 + 1) * 1024 + cb] = s10; Ps[(r0 + 1) * 1024 + cb + 1] = s11;
        }
        __syncthreads();
        {   // softmax: warp w owns row w
            int r = warp;
            float* row = Ps + r * 1024;
            float m = -1e30f;
            for (int i = lane; i < 1024; i += 32) m = fmaxf(m, row[i]);
#pragma unroll
            for (int o = 16; o > 0; o >>= 1) m = fmaxf(m, __shfl_xor_sync(0xffffffffu, m, o));
            float s = 0.f;
            for (int i = lane; i < 1024; i += 32) {
                float e = __expf(row[i] - m);
                row[i] = e;
                s += e;
            }
#pragma unroll
            for (int o = 16; o > 0; o >>= 1) s += __shfl_xor_sync(0xffffffffu, s, o);
            float inv = 1.f / s;
            float* arow = attnw + (qbase + r) * 1024;
            if (h == 0) {
                for (int i = lane; i < 1024; i += 32) {
                    float p = row[i] * inv; row[i] = p; arow[i] = 0.25f * p;
                }
            } else {
                for (int i = lane; i < 1024; i += 32) {
                    float p = row[i] * inv; row[i] = p; arow[i] += 0.25f * p;
                }
            }
        }
        {   // ctx[r, h*32+d] = sum_k p[r,k] * V[k, h*32+d]; warp==row so no sync needed
            int r = tid >> 5, d = tid & 31;
            const float* prow = Ps + r * 1024;
            const float* vcol = g_v + h * 32 + d;
            float a0 = 0, a1 = 0, a2 = 0, a3 = 0;
#pragma unroll 2
            for (int k = 0; k < 1024; k += 4) {
                a0 += prow[k]     * vcol[(k)     * 128];
                a1 += prow[k + 1] * vcol[(k + 1) * 128];
                a2 += prow[k + 2] * vcol[(k + 2) * 128];
                a3 += prow[k + 3] * vcol[(k + 3) * 128];
            }
            g_ctx[(qbase + r) * 128 + h * 32 + d] = a0 + a1 + a2 + a3;
        }
        __syncthreads();
    }
}

// ---------------- out projection: attended = ctx @ out_w^T + out_b ----------
__global__ __launch_bounds__(128) void outproj_kernel(const float* __restrict__ W,
                                                      const float* __restrict__ b) {
    __shared__ float xs[8 * 128];
    int rb = blockIdx.x * 8;
    for (int i = threadIdx.x; i < 1024; i += 128) xs[i] = g_ctx[rb * 128 + i];
    __syncthreads();
    int j = threadIdx.x;
    const float4* w4 = (const float4*)(W + j * 128);
    const float4* xs4 = (const float4*)xs;
    float acc[8] = {0, 0, 0, 0, 0, 0, 0, 0};
#pragma unroll 8
    for (int i4 = 0; i4 < 32; i4++) {
        float4 w = w4[i4];
#pragma unroll
        for (int r = 0; r < 8; r++) {
            float4 xv = xs4[r * 32 + i4];
            acc[r] += w.x * xv.x + w.y * xv.y + w.z * xv.z + w.w * xv.w;
        }
    }
    float bj = b[j];
#pragma unroll
    for (int r = 0; r < 8; r++) g_att[(rb + r) * 128 + j] = acc[r] + bj;
}

// ---------------- t1 = task @ W1[:, :128]^T ; n1 = attended @ W1[:, 128:]^T --
// grid 256: first 128 blocks -> t1, last 128 -> n1. (b1 added later in h1.)
__global__ __launch_bounds__(256) void t1n1_kernel(const float* __restrict__ task,
                                                   const float* __restrict__ W1) {
    __shared__ float xs[8 * 128];
    int half = blockIdx.x >> 7;
    int rb = (blockIdx.x & 127) * 8;
    const float* src = half ? g_att : task;
    for (int i = threadIdx.x; i < 1024; i += 256) xs[i] = src[rb * 128 + i];
    __syncthreads();
    int j = threadIdx.x;  // 0..255 output feature
    const float4* w4 = (const float4*)(W1 + j * 256 + half * 128);
    const float4* xs4 = (const float4*)xs;
    float acc[8] = {0, 0, 0, 0, 0, 0, 0, 0};
#pragma unroll 8
    for (int i4 = 0; i4 < 32; i4++) {
        float4 w = w4[i4];
#pragma unroll
        for (int r = 0; r < 8; r++) {
            float4 xv = xs4[r * 32 + i4];
            acc[r] += w.x * xv.x + w.y * xv.y + w.z * xv.z + w.w * xv.w;
        }
    }
    float* dst = half ? g_n1 : g_t1;
#pragma unroll
    for (int r = 0; r < 8; r++) dst[(rb + r) * 256 + j] = acc[r];
}

// ---------------- coordination head (tiny, 1 block) --------------------------
__global__ __launch_bounds__(256) void coord_kernel(const float* __restrict__ Wc1,
                                                    const float* __restrict__ bc1,
                                                    const float* __restrict__ Wc2,
                                                    const float* __restrict__ bc2,
                                                    float* __restrict__ outc) {
    __shared__ float gs[128];
    __shared__ float hid[256];
    int tid = threadIdx.x;
    if (tid < 128) {
        float a0 = 0, a1 = 0, a2 = 0, a3 = 0;
        for (int i = 0; i < 1024; i += 4) {
            a0 += g_att[(i)     * 128 + tid];
            a1 += g_att[(i + 1) * 128 + tid];
            a2 += g_att[(i + 2) * 128 + tid];
            a3 += g_att[(i + 3) * 128 + tid];
        }
        gs[tid] = (a0 + a1 + a2 + a3) * (1.0f / 1024.0f);
    }
    __syncthreads();
    {
        const float* w = Wc1 + tid * 128;
        float acc = 0;
#pragma unroll 8
        for (int c = 0; c < 128; c++) acc += gs[c] * w[c];
        hid[tid] = fmaxf(acc + bc1[tid], 0.f);
    }
    __syncthreads();
    if (tid < 32) {
        const float* w = Wc2 + tid * 256;
        float acc = 0;
#pragma unroll 8
        for (int c = 0; c < 256; c++) acc += hid[c] * w[c];
        outc[tid] = acc + bc2[tid];
    }
}

// ---------------- matching scores: the 68.7 GFLOP pairwise MLP ---------------
// sigmoid( W3 . relu( W2 @ relu(t1[t]+n1[n]+b1) + b2 ) + b3 ) for 1M (t,n) pairs
// Persistent blocks; W2 (tf32) resident in smem; per-tile h1 (64 pairs) in smem;
// tf32 mma.sync m16n8k8, warp tile 32x64, block tile 64(pairs) x 128(k).
#define MATCH_SMEM_FLOATS (128 * 260 + 64 * 260 + 256 + 128 + 128 + 256)
#define MATCH_SMEM_BYTES (MATCH_SMEM_FLOATS * 4)

__global__ __launch_bounds__(256) void matching_kernel(const float* __restrict__ W2,
                                                       const float* __restrict__ b2,
                                                       const float* __restrict__ W3,
                                                       const float* __restrict__ b1,
                                                       const float* __restrict__ b3p,
                                                       float* __restrict__ out) {
    extern __shared__ float sm[];
    float* W2s = sm;                  // [128][260] (tf32-rounded)
    float* h1s = W2s + 128 * 260;     // [64][260]  (tf32-rounded)
    float* red = h1s + 64 * 260;      // [64][4] cross-warp partials
    float* b2s = red + 256;           // [128]
    float* W3s = b2s + 128;           // [128]
    float* b1s = W3s + 128;           // [256]

    int tid = threadIdx.x;
    for (int i = tid; i < 128 * 256; i += 256) {
        int r = i >> 8, c = i & 255;
        float v = W2[i];
        uint32_t u;
        asm("cvt.rna.tf32.f32 %0, %1;" : "=r"(u) : "f"(v));
        W2s[r * 260 + c] = __uint_as_float(u);
    }
    if (tid < 128) { b2s[tid] = b2[tid]; W3s[tid] = W3[tid]; }
    b1s[tid] = b1[tid];
    float b3v = b3p[0];

    int lane = tid & 31, warp = tid >> 5;
    int gid = lane >> 2, tig = lane & 3;
    int wm = warp >> 2;          // 0..1  -> 32 pair-rows
    int wn = (warp & 3) * 32;    // 0,32,64,96 -> 32 k-cols

    for (int tile = blockIdx.x; tile < 16384; tile += gridDim.x) {
        int tbase = (tile >> 7) << 3;   // 8 task rows
        int nbase = (tile & 127) << 3;  // 8 node rows
        __syncthreads();  // prev tile fully consumed (h1s, red)
        for (int i = tid; i < 64 * 256; i += 256) {
            int p = i >> 8, c = i & 255;
            int t = tbase + (p >> 3), n = nbase + (p & 7);
            float v = fmaxf(g_t1[t * 256 + c] + g_n1[n * 256 + c] + b1s[c], 0.f);
            uint32_t u;
            asm("cvt.rna.tf32.f32 %0, %1;" : "=r"(u) : "f"(v));
            h1s[p * 260 + c] = __uint_as_float(u);
        }
        __syncthreads();

        float acc[2][4][4];
#pragma unroll
        for (int mt = 0; mt < 2; mt++)
#pragma unroll
            for (int nt = 0; nt < 4; nt++)
#pragma unroll
                for (int i = 0; i < 4; i++) acc[mt][nt][i] = 0.f;

#pragma unroll 2
        for (int c = 0; c < 256; c += 8) {
            uint32_t a[2][4], bb[4][2];
#pragma unroll
            for (int mt = 0; mt < 2; mt++) {
                int row = wm * 32 + mt * 16 + gid;
                a[mt][0] = __float_as_uint(h1s[row * 260 + c + tig]);
                a[mt][1] = __float_as_uint(h1s[(row + 8) * 260 + c + tig]);
                a[mt][2] = __float_as_uint(h1s[row * 260 + c + tig + 4]);
                a[mt][3] = __float_as_uint(h1s[(row + 8) * 260 + c + tig + 4]);
            }
#pragma unroll
            for (int nt = 0; nt < 4; nt++) {
                int n0 = wn + nt * 8 + gid;
                bb[nt][0] = __float_as_uint(W2s[n0 * 260 + c + tig]);
                bb[nt][1] = __float_as_uint(W2s[n0 * 260 + c + tig + 4]);
            }
#pragma unroll
            for (int mt = 0; mt < 2; mt++)
#pragma unroll
                for (int nt = 0; nt < 4; nt++)
                    asm volatile(
                        "mma.sync.aligned.m16n8k8.row.col.f32.tf32.tf32.f32 "
                        "{%0,%1,%2,%3}, {%4,%5,%6,%7}, {%8,%9}, {%0,%1,%2,%3};"
                        : "+f"(acc[mt][nt][0]), "+f"(acc[mt][nt][1]),
                          "+f"(acc[mt][nt][2]), "+f"(acc[mt][nt][3])
                        : "r"(a[mt][0]), "r"(a[mt][1]), "r"(a[mt][2]), "r"(a[mt][3]),
                          "r"(bb[nt][0]), "r"(bb[nt][1]));
        }

        // fused epilogue: z_partial = sum_k relu(C + b2[k]) * W3[k]
        float part[2][2] = {{0, 0}, {0, 0}};
#pragma unroll
        for (int mt = 0; mt < 2; mt++)
#pragma unroll
            for (int nt = 0; nt < 4; nt++) {
                int cb = wn + nt * 8 + tig * 2;
                float w3a = W3s[cb], w3b = W3s[cb + 1];
                float ba = b2s[cb], bbv = b2s[cb + 1];
                part[mt][0] += fmaxf(acc[mt][nt][0] + ba, 0.f) * w3a +
                               fmaxf(acc[mt][nt][1] + bbv, 0.f) * w3b;
                part[mt][1] += fmaxf(acc[mt][nt][2] + ba, 0.f) * w3a +
                               fmaxf(acc[mt][nt][3] + bbv, 0.f) * w3b;
            }
#pragma unroll
        for (int mt = 0; mt < 2; mt++)
#pragma unroll
            for (int hh = 0; hh < 2; hh++) {
                float v = part[mt][hh];
                v += __shfl_xor_sync(0xffffffffu, v, 1);
                v += __shfl_xor_sync(0xffffffffu, v, 2);
                part[mt][hh] = v;
            }
        if (tig == 0) {
            int q = warp & 3;
#pragma unroll
            for (int mt = 0; mt < 2; mt++) {
                int row = wm * 32 + mt * 16 + gid;
                red[row * 4 + q] = part[mt][0];
                red[(row + 8) * 4 + q] = part[mt][1];
            }
        }
        __syncthreads();
        if (tid < 64) {
            float z = red[tid * 4] + red[tid * 4 + 1] + red[tid * 4 + 2] +
                      red[tid * 4 + 3] + b3v;
            float s = 1.f / (1.f + __expf(-z));
            int t = tbase + (tid >> 3), n = nbase + (tid & 7);
            out[t * 1024 + n] = s;
        }
    }
}

// ---------------- launch ------------------------------------------------------
extern "C" void kernel_launch(void* const* d_in, const int* in_sizes, int n_in,
                              void* d_out, int out_size) {
    const float* node_states = (const float*)d_in[0];
    const float* task_features = (const float*)d_in[1];
    const float* in_proj_w = (const float*)d_in[2];
    const float* in_proj_b = (const float*)d_in[3];
    const float* out_w = (const float*)d_in[4];
    const float* out_b = (const float*)d_in[5];
    const float* W1 = (const float*)d_in[6];
    const float* b1 = (const float*)d_in[7];
    const float* W2 = (const float*)d_in[8];
    const float* b2 = (const float*)d_in[9];
    const float* W3 = (const float*)d_in[10];
    const float* b3 = (const float*)d_in[11];
    const float* Wc1 = (const float*)d_in[12];
    const float* bc1 = (const float*)d_in[13];
    const float* Wc2 = (const float*)d_in[14];
    const float* bc2 = (const float*)d_in[15];

    float* out = (float*)d_out;
    float* matching = out;                       // [1024*1024]
    float* coord = out + 1024 * 1024;            // [32]
    float* attnw = out + 1024 * 1024 + 32;       // [1024*1024]

    cudaFuncSetAttribute((const void*)attn_kernel,
                         cudaFuncAttributeMaxDynamicSharedMemorySize, ATTN_SMEM_BYTES);
    cudaFuncSetAttribute((const void*)matching_kernel,
                         cudaFuncAttributeMaxDynamicSharedMemorySize, MATCH_SMEM_BYTES);

    qkv_kernel<<<128, 384>>>(node_states, in_proj_w, in_proj_b);
    attn_kernel<<<128, 256, ATTN_SMEM_BYTES>>>(attnw);
    outproj_kernel<<<128, 128>>>(out_w, out_b);
    t1n1_kernel<<<256, 256>>>(task_features, W1);
    coord_kernel<<<1, 256>>>(Wc1, bc1, Wc2, bc2, coord);
    matching_kernel<<<148, 256, MATCH_SMEM_BYTES>>>(W2, b2, W3, b1, b3, matching);
}

// round 5
// speedup vs baseline: 1.3839x; 1.3839x over previous
#include <cuda_runtime.h>
#include <cuda_bf16.h>
#include <cstdint>

// ---------------- scratch (no allocation allowed -> __device__ globals) -----
__device__ float g_q[1024 * 128];
__device__ float g_k[1024 * 128];
__device__ float g_v[1024 * 128];
__device__ float g_ctx[1024 * 128];
__device__ float g_att[1024 * 128];
__device__ float g_t1[1024 * 256];
__device__ float g_n1[1024 * 256];

// ---------------- QKV projection: q/k/v = x @ Wqkv^T + b --------------------
__global__ __launch_bounds__(384) void qkv_kernel(const float* __restrict__ x,
                                                  const float* __restrict__ W,
                                                  const float* __restrict__ b) {
    __shared__ float xs[8 * 128];
    int rb = blockIdx.x * 8;
    for (int i = threadIdx.x; i < 1024; i += 384) xs[i] = x[rb * 128 + i];
    __syncthreads();
    int j = threadIdx.x;
    const float4* w4 = (const float4*)(W + j * 128);
    const float4* xs4 = (const float4*)xs;
    float acc[8] = {0, 0, 0, 0, 0, 0, 0, 0};
#pragma unroll 8
    for (int i4 = 0; i4 < 32; i4++) {
        float4 w = w4[i4];
#pragma unroll
        for (int r = 0; r < 8; r++) {
            float4 xv = xs4[r * 32 + i4];
            acc[r] += w.x * xv.x + w.y * xv.y + w.z * xv.z + w.w * xv.w;
        }
    }
    float bj = b[j];
    float* dst;
    int col;
    if (j < 128) { dst = g_q; col = j; }
    else if (j < 256) { dst = g_k; col = j - 128; }
    else { dst = g_v; col = j - 256; }
#pragma unroll
    for (int r = 0; r < 8; r++) dst[(rb + r) * 128 + col] = acc[r] + bj;
}

// ---------------- attention (fp32, full matrix needed: attn_w is an output) -
#define ATTN_SMEM_BYTES ((8 * 1024 + 128 * 33 + 8 * 32) * 4)
__global__ __launch_bounds__(256) void attn_kernel(float* __restrict__ attnw) {
    extern __shared__ float sm[];
    float* Ps = sm;
    float* Ks = sm + 8 * 1024;
    float* Qs = Ks + 128 * 33;
    int tid = threadIdx.x, lane = tid & 31, warp = tid >> 5;
    int qbase = blockIdx.x * 8;

    for (int h = 0; h < 4; h++) {
        {
            int r = tid >> 5, d = tid & 31;
            Qs[tid] = g_q[(qbase + r) * 128 + h * 32 + d] * 0.17677669529663687f;
        }
        for (int kc = 0; kc < 8; kc++) {
            __syncthreads();
            for (int i = tid; i < 4096; i += 256) {
                int kk = i >> 5, d = i & 31;
                Ks[kk * 33 + d] = g_k[(kc * 128 + kk) * 128 + h * 32 + d];
            }
            __syncthreads();
            int r0 = (tid >> 6) * 2;
            int k0 = (tid & 63) * 2;
            float s00 = 0, s01 = 0, s10 = 0, s11 = 0;
#pragma unroll
            for (int d = 0; d < 32; d++) {
                float qa = Qs[r0 * 32 + d], qb = Qs[(r0 + 1) * 32 + d];
                float ka = Ks[k0 * 33 + d], kb = Ks[(k0 + 1) * 33 + d];
                s00 += qa * ka; s01 += qa * kb;
                s10 += qb * ka; s11 += qb * kb;
            }
            int cb = kc * 128 + k0;
            Ps[r0 * 1024 + cb] = s00;       Ps[r0 * 1024 + cb + 1] = s01;
            Ps[(r0 + 1) * 1024 + cb] = s10; Ps[(r0 + 1) * 1024 + cb + 1] = s11;
        }
        __syncthreads();
        {
            int r = warp;
            float* row = Ps + r * 1024;
            float m = -1e30f;
            for (int i = lane; i < 1024; i += 32) m = fmaxf(m, row[i]);
#pragma unroll
            for (int o = 16; o > 0; o >>= 1) m = fmaxf(m, __shfl_xor_sync(0xffffffffu, m, o));
            float s = 0.f;
            for (int i = lane; i < 1024; i += 32) {
                float e = __expf(row[i] - m);
                row[i] = e;
                s += e;
            }
#pragma unroll
            for (int o = 16; o > 0; o >>= 1) s += __shfl_xor_sync(0xffffffffu, s, o);
            float inv = 1.f / s;
            float* arow = attnw + (qbase + r) * 1024;
            if (h == 0) {
                for (int i = lane; i < 1024; i += 32) {
                    float p = row[i] * inv; row[i] = p; arow[i] = 0.25f * p;
                }
            } else {
                for (int i = lane; i < 1024; i += 32) {
                    float p = row[i] * inv; row[i] = p; arow[i] += 0.25f * p;
                }
            }
        }
        {
            int r = tid >> 5, d = tid & 31;
            const float* prow = Ps + r * 1024;
            const float* vcol = g_v + h * 32 + d;
            float a0 = 0, a1 = 0, a2 = 0, a3 = 0;
#pragma unroll 2
            for (int k = 0; k < 1024; k += 4) {
                a0 += prow[k]     * vcol[(k)     * 128];
                a1 += prow[k + 1] * vcol[(k + 1) * 128];
                a2 += prow[k + 2] * vcol[(k + 2) * 128];
                a3 += prow[k + 3] * vcol[(k + 3) * 128];
            }
            g_ctx[(qbase + r) * 128 + h * 32 + d] = a0 + a1 + a2 + a3;
        }
        __syncthreads();
    }
}

// ---------------- out projection ---------------------------------------------
__global__ __launch_bounds__(128) void outproj_kernel(const float* __restrict__ W,
                                                      const float* __restrict__ b) {
    __shared__ float xs[8 * 128];
    int rb = blockIdx.x * 8;
    for (int i = threadIdx.x; i < 1024; i += 128) xs[i] = g_ctx[rb * 128 + i];
    __syncthreads();
    int j = threadIdx.x;
    const float4* w4 = (const float4*)(W + j * 128);
    const float4* xs4 = (const float4*)xs;
    float acc[8] = {0, 0, 0, 0, 0, 0, 0, 0};
#pragma unroll 8
    for (int i4 = 0; i4 < 32; i4++) {
        float4 w = w4[i4];
#pragma unroll
        for (int r = 0; r < 8; r++) {
            float4 xv = xs4[r * 32 + i4];
            acc[r] += w.x * xv.x + w.y * xv.y + w.z * xv.z + w.w * xv.w;
        }
    }
    float bj = b[j];
#pragma unroll
    for (int r = 0; r < 8; r++) g_att[(rb + r) * 128 + j] = acc[r] + bj;
}

// ---------------- t1 = task @ W1[:, :128]^T ; n1 = attended @ W1[:, 128:]^T --
__global__ __launch_bounds__(256) void t1n1_kernel(const float* __restrict__ task,
                                                   const float* __restrict__ W1) {
    __shared__ float xs[8 * 128];
    int half = blockIdx.x >> 7;
    int rb = (blockIdx.x & 127) * 8;
    const float* src = half ? g_att : task;
    for (int i = threadIdx.x; i < 1024; i += 256) xs[i] = src[rb * 128 + i];
    __syncthreads();
    int j = threadIdx.x;
    const float4* w4 = (const float4*)(W1 + j * 256 + half * 128);
    const float4* xs4 = (const float4*)xs;
    float acc[8] = {0, 0, 0, 0, 0, 0, 0, 0};
#pragma unroll 8
    for (int i4 = 0; i4 < 32; i4++) {
        float4 w = w4[i4];
#pragma unroll
        for (int r = 0; r < 8; r++) {
            float4 xv = xs4[r * 32 + i4];
            acc[r] += w.x * xv.x + w.y * xv.y + w.z * xv.z + w.w * xv.w;
        }
    }
    float* dst = half ? g_n1 : g_t1;
#pragma unroll
    for (int r = 0; r < 8; r++) dst[(rb + r) * 256 + j] = acc[r];
}

// ---------------- coordination head (tiny) -----------------------------------
__global__ __launch_bounds__(256) void coord_kernel(const float* __restrict__ Wc1,
                                                    const float* __restrict__ bc1,
                                                    const float* __restrict__ Wc2,
                                                    const float* __restrict__ bc2,
                                                    float* __restrict__ outc) {
    __shared__ float gs[128];
    __shared__ float hid[256];
    int tid = threadIdx.x;
    if (tid < 128) {
        float a0 = 0, a1 = 0, a2 = 0, a3 = 0;
        for (int i = 0; i < 1024; i += 4) {
            a0 += g_att[(i)     * 128 + tid];
            a1 += g_att[(i + 1) * 128 + tid];
            a2 += g_att[(i + 2) * 128 + tid];
            a3 += g_att[(i + 3) * 128 + tid];
        }
        gs[tid] = (a0 + a1 + a2 + a3) * (1.0f / 1024.0f);
    }
    __syncthreads();
    {
        const float* w = Wc1 + tid * 128;
        float acc = 0;
#pragma unroll 8
        for (int c = 0; c < 128; c++) acc += gs[c] * w[c];
        hid[tid] = fmaxf(acc + bc1[tid], 0.f);
    }
    __syncthreads();
    if (tid < 32) {
        const float* w = Wc2 + tid * 256;
        float acc = 0;
#pragma unroll 8
        for (int c = 0; c < 256; c++) acc += hid[c] * w[c];
        outc[tid] = acc + bc2[tid];
    }
}

// ---------------- matching scores: 68.7 GFLOP pairwise MLP (bf16 HMMA) -------
// Block tile: 128 pairs (16 t x 8 n) x 128 k-out, K=256.
// 8 warps as 4(m) x 2(n): warp tile 32 pairs x 64 k.
// h1 & W2 in smem as bf16 with 264-element row stride (conflict-free LDSM/STS).
// mma.sync.m16n8k16 bf16, fragments via ldmatrix.
#define MSTRIDE 264
#define MATCH_SMEM_BYTES (2 * 128 * MSTRIDE * 2 + 128 * 4 + 128 * 4 + 128 * 2 * 4)

__global__ __launch_bounds__(256) void matching_kernel(const float* __restrict__ W2,
                                                       const float* __restrict__ b2,
                                                       const float* __restrict__ W3,
                                                       const float* __restrict__ b1,
                                                       const float* __restrict__ b3p,
                                                       float* __restrict__ out) {
    extern __shared__ char smraw[];
    __nv_bfloat16* W2s = (__nv_bfloat16*)smraw;                    // [128][264]
    __nv_bfloat16* h1s = W2s + 128 * MSTRIDE;                      // [128][264]
    float* b2s = (float*)(h1s + 128 * MSTRIDE);                    // [128]
    float* W3s = b2s + 128;                                        // [128]
    float* red = W3s + 128;                                        // [128][2]

    int tid = threadIdx.x, lane = tid & 31, warp = tid >> 5;

    // ---- one-time: W2 (fp32 -> bf16) resident in smem, biases --------------
    for (int i = tid; i < 128 * 256; i += 256) {
        int r = i >> 8, c = i & 255;
        W2s[r * MSTRIDE + c] = __float2bfloat16_rn(W2[i]);
    }
    if (tid < 128) { b2s[tid] = b2[tid]; W3s[tid] = W3[tid]; }
    float b3v = b3p[0];

    // per-lane b1 registers: lane owns columns lane*8 .. lane*8+7
    float b1r[8];
#pragma unroll
    for (int j = 0; j < 8; j++) b1r[j] = b1[lane * 8 + j];

    // warp tiling
    int m0w = (warp >> 1) * 32;      // pair-row base of warp (0,32,64,96)
    int n0w = (warp & 1) * 64;       // k-out base of warp (0 or 64)
    int gid = lane >> 2, tig = lane & 3;

    // ldmatrix per-lane shared addresses (byte offsets added per k-step)
    uint32_t h1_base = (uint32_t)__cvta_generic_to_shared(h1s);
    uint32_t w2_base = (uint32_t)__cvta_generic_to_shared(W2s);
    uint32_t aAddr[2];
#pragma unroll
    for (int mt = 0; mt < 2; mt++)
        aAddr[mt] = h1_base +
            (uint32_t)(((m0w + mt * 16 + (lane & 15)) * MSTRIDE + ((lane >> 4) * 8)) * 2);
    int rowB = (lane & 7) + (((lane >> 4) & 1) << 3);
    int koffB = ((lane >> 3) & 1) * 8;
    uint32_t bAddr[4];
#pragma unroll
    for (int j = 0; j < 4; j++)
        bAddr[j] = w2_base + (uint32_t)(((n0w + j * 16 + rowB) * MSTRIDE + koffB) * 2);

    const float4* t14 = (const float4*)g_t1;
    const float4* n14 = (const float4*)g_n1;

    for (int tile = blockIdx.x; tile < 8192; tile += gridDim.x) {
        int tbase = (tile >> 7) * 16;   // 16 task rows
        int nbase = (tile & 127) * 8;   // 8 node rows
        __syncthreads();  // prev tile fully consumed (h1s, red)

        // ---- build h1 tile: 128 pairs x 256 ch, bf16, relu(t1+n1+b1) ------
        // warp handles 16 pairs; lane handles 8 channels (lane*8..+7)
#pragma unroll 4
        for (int i = 0; i < 16; i++) {
            int p = warp * 16 + i;
            int t = tbase + (p >> 3), n = nbase + (p & 7);
            float4 ta = t14[(t * 256 + lane * 8) >> 2];
            float4 tb = t14[((t * 256 + lane * 8) >> 2) + 1];
            float4 na = n14[(n * 256 + lane * 8) >> 2];
            float4 nb = n14[((n * 256 + lane * 8) >> 2) + 1];
            float v0 = fmaxf(ta.x + na.x + b1r[0], 0.f);
            float v1 = fmaxf(ta.y + na.y + b1r[1], 0.f);
            float v2 = fmaxf(ta.z + na.z + b1r[2], 0.f);
            float v3 = fmaxf(ta.w + na.w + b1r[3], 0.f);
            float v4 = fmaxf(tb.x + nb.x + b1r[4], 0.f);
            float v5 = fmaxf(tb.y + nb.y + b1r[5], 0.f);
            float v6 = fmaxf(tb.z + nb.z + b1r[6], 0.f);
            float v7 = fmaxf(tb.w + nb.w + b1r[7], 0.f);
            uint4 pk;
            asm("cvt.rn.bf16x2.f32 %0, %1, %2;" : "=r"(pk.x) : "f"(v1), "f"(v0));
            asm("cvt.rn.bf16x2.f32 %0, %1, %2;" : "=r"(pk.y) : "f"(v3), "f"(v2));
            asm("cvt.rn.bf16x2.f32 %0, %1, %2;" : "=r"(pk.z) : "f"(v5), "f"(v4));
            asm("cvt.rn.bf16x2.f32 %0, %1, %2;" : "=r"(pk.w) : "f"(v7), "f"(v6));
            *(uint4*)(h1s + p * MSTRIDE + lane * 8) = pk;
        }
        __syncthreads();

        // ---- MMA: warp tile 32x64, K=256 in 16 steps of k16 ----------------
        float acc[2][8][4];
#pragma unroll
        for (int mt = 0; mt < 2; mt++)
#pragma unroll
            for (int nt = 0; nt < 8; nt++)
#pragma unroll
                for (int i = 0; i < 4; i++) acc[mt][nt][i] = 0.f;

#pragma unroll 4
        for (int ks = 0; ks < 16; ks++) {
            uint32_t cb = ks * 32;  // 16 bf16 = 32 bytes
            uint32_t a[2][4], bq[4][4];
#pragma unroll
            for (int mt = 0; mt < 2; mt++)
                asm volatile(
                    "ldmatrix.sync.aligned.m8n8.x4.shared.b16 {%0,%1,%2,%3}, [%4];"
                    : "=r"(a[mt][0]), "=r"(a[mt][1]), "=r"(a[mt][2]), "=r"(a[mt][3])
                    : "r"(aAddr[mt] + cb));
#pragma unroll
            for (int j = 0; j < 4; j++)
                asm volatile(
                    "ldmatrix.sync.aligned.m8n8.x4.shared.b16 {%0,%1,%2,%3}, [%4];"
                    : "=r"(bq[j][0]), "=r"(bq[j][1]), "=r"(bq[j][2]), "=r"(bq[j][3])
                    : "r"(bAddr[j] + cb));
#pragma unroll
            for (int mt = 0; mt < 2; mt++)
#pragma unroll
                for (int j = 0; j < 4; j++) {
                    asm volatile(
                        "mma.sync.aligned.m16n8k16.row.col.f32.bf16.bf16.f32 "
                        "{%0,%1,%2,%3}, {%4,%5,%6,%7}, {%8,%9}, {%0,%1,%2,%3};"
                        : "+f"(acc[mt][2 * j][0]), "+f"(acc[mt][2 * j][1]),
                          "+f"(acc[mt][2 * j][2]), "+f"(acc[mt][2 * j][3])
                        : "r"(a[mt][0]), "r"(a[mt][1]), "r"(a[mt][2]), "r"(a[mt][3]),
                          "r"(bq[j][0]), "r"(bq[j][1]));
                    asm volatile(
                        "mma.sync.aligned.m16n8k16.row.col.f32.bf16.bf16.f32 "
                        "{%0,%1,%2,%3}, {%4,%5,%6,%7}, {%8,%9}, {%0,%1,%2,%3};"
                        : "+f"(acc[mt][2 * j + 1][0]), "+f"(acc[mt][2 * j + 1][1]),
                          "+f"(acc[mt][2 * j + 1][2]), "+f"(acc[mt][2 * j + 1][3])
                        : "r"(a[mt][0]), "r"(a[mt][1]), "r"(a[mt][2]), "r"(a[mt][3]),
                          "r"(bq[j][2]), "r"(bq[j][3]));
                }
        }

        // ---- fused epilogue: z_part = sum_k relu(C + b2[k]) * W3[k] --------
        float part[2][2] = {{0, 0}, {0, 0}};
#pragma unroll
        for (int mt = 0; mt < 2; mt++)
#pragma unroll
            for (int nt = 0; nt < 8; nt++) {
                int cb = n0w + nt * 8 + tig * 2;
                float w3a = W3s[cb], w3b = W3s[cb + 1];
                float ba = b2s[cb], bb = b2s[cb + 1];
                part[mt][0] += fmaxf(acc[mt][nt][0] + ba, 0.f) * w3a +
                               fmaxf(acc[mt][nt][1] + bb, 0.f) * w3b;
                part[mt][1] += fmaxf(acc[mt][nt][2] + ba, 0.f) * w3a +
                               fmaxf(acc[mt][nt][3] + bb, 0.f) * w3b;
            }
#pragma unroll
        for (int mt = 0; mt < 2; mt++)
#pragma unroll
            for (int hh = 0; hh < 2; hh++) {
                float v = part[mt][hh];
                v += __shfl_xor_sync(0xffffffffu, v, 1);
                v += __shfl_xor_sync(0xffffffffu, v, 2);
                part[mt][hh] = v;
            }
        if (tig == 0) {
            int half = warp & 1;
#pragma unroll
            for (int mt = 0; mt < 2; mt++) {
                int r0 = m0w + mt * 16 + gid;
                red[r0 * 2 + half] = part[mt][0];
                red[(r0 + 8) * 2 + half] = part[mt][1];
            }
        }
        __syncthreads();
        if (tid < 128) {
            float z = red[tid * 2] + red[tid * 2 + 1] + b3v;
            float s = 1.f / (1.f + __expf(-z));
            int t = tbase + (tid >> 3), n = nbase + (tid & 7);
            out[t * 1024 + n] = s;
        }
    }
}

// ---------------- launch ------------------------------------------------------
extern "C" void kernel_launch(void* const* d_in, const int* in_sizes, int n_in,
                              void* d_out, int out_size) {
    const float* node_states = (const float*)d_in[0];
    const float* task_features = (const float*)d_in[1];
    const float* in_proj_w = (const float*)d_in[2];
    const float* in_proj_b = (const float*)d_in[3];
    const float* out_w = (const float*)d_in[4];
    const float* out_b = (const float*)d_in[5];
    const float* W1 = (const float*)d_in[6];
    const float* b1 = (const float*)d_in[7];
    const float* W2 = (const float*)d_in[8];
    const float* b2 = (const float*)d_in[9];
    const float* W3 = (const float*)d_in[10];
    const float* b3 = (const float*)d_in[11];
    const float* Wc1 = (const float*)d_in[12];
    const float* bc1 = (const float*)d_in[13];
    const float* Wc2 = (const float*)d_in[14];
    const float* bc2 = (const float*)d_in[15];

    float* out = (float*)d_out;
    float* matching = out;                       // [1024*1024]
    float* coord = out + 1024 * 1024;            // [32]
    float* attnw = out + 1024 * 1024 + 32;       // [1024*1024]

    cudaFuncSetAttribute((const void*)attn_kernel,
                         cudaFuncAttributeMaxDynamicSharedMemorySize, ATTN_SMEM_BYTES);
    cudaFuncSetAttribute((const void*)matching_kernel,
                         cudaFuncAttributeMaxDynamicSharedMemorySize, MATCH_SMEM_BYTES);

    qkv_kernel<<<128, 384>>>(node_states, in_proj_w, in_proj_b);
    attn_kernel<<<128, 256, ATTN_SMEM_BYTES>>>(attnw);
    outproj_kernel<<<128, 128>>>(out_w, out_b);
    t1n1_kernel<<<256, 256>>>(task_features, W1);
    coord_kernel<<<1, 256>>>(Wc1, bc1, Wc2, bc2, coord);
    matching_kernel<<<148, 256, MATCH_SMEM_BYTES>>>(W2, b2, W3, b1, b3, matching);
}

// round 10
// speedup vs baseline: 2.3857x; 1.7239x over previous
#include <cuda_runtime.h>
#include <cuda_bf16.h>
#include <cstdint>

// ---------------- scratch (no allocation allowed -> __device__ globals) -----
__device__ float g_q[1024 * 128];
__device__ float g_k[1024 * 128];
__device__ float g_v[1024 * 128];
__device__ float g_ctx[1024 * 128];
__device__ float g_att[1024 * 128];
__device__ float g_t1[1024 * 256];
__device__ float g_n1[1024 * 256];

// ---------------- QKV projection: q/k/v = x @ Wqkv^T + b --------------------
__global__ __launch_bounds__(384) void qkv_kernel(const float* __restrict__ x,
                                                  const float* __restrict__ W,
                                                  const float* __restrict__ b) {
    __shared__ float xs[8 * 128];
    int rb = blockIdx.x * 8;
    for (int i = threadIdx.x; i < 1024; i += 384) xs[i] = x[rb * 128 + i];
    __syncthreads();
    int j = threadIdx.x;
    const float4* w4 = (const float4*)(W + j * 128);
    const float4* xs4 = (const float4*)xs;
    float acc[8] = {0, 0, 0, 0, 0, 0, 0, 0};
#pragma unroll 8
    for (int i4 = 0; i4 < 32; i4++) {
        float4 w = w4[i4];
#pragma unroll
        for (int r = 0; r < 8; r++) {
            float4 xv = xs4[r * 32 + i4];
            acc[r] += w.x * xv.x + w.y * xv.y + w.z * xv.z + w.w * xv.w;
        }
    }
    float bj = b[j];
    float* dst;
    int col;
    if (j < 128) { dst = g_q; col = j; }
    else if (j < 256) { dst = g_k; col = j - 128; }
    else { dst = g_v; col = j - 256; }
#pragma unroll
    for (int r = 0; r < 8; r++) dst[(rb + r) * 128 + col] = acc[r] + bj;
}

// ---------------- attention (fp32, full matrix needed: attn_w is an output) -
#define ATTN_SMEM_BYTES ((8 * 1024 + 128 * 33 + 8 * 32) * 4)
__global__ __launch_bounds__(256) void attn_kernel(float* __restrict__ attnw) {
    extern __shared__ float sm[];
    float* Ps = sm;
    float* Ks = sm + 8 * 1024;
    float* Qs = Ks + 128 * 33;
    int tid = threadIdx.x, lane = tid & 31, warp = tid >> 5;
    int qbase = blockIdx.x * 8;

    for (int h = 0; h < 4; h++) {
        {
            int r = tid >> 5, d = tid & 31;
            Qs[tid] = g_q[(qbase + r) * 128 + h * 32 + d] * 0.17677669529663687f;
        }
        for (int kc = 0; kc < 8; kc++) {
            __syncthreads();
            for (int i = tid; i < 4096; i += 256) {
                int kk = i >> 5, d = i & 31;
                Ks[kk * 33 + d] = g_k[(kc * 128 + kk) * 128 + h * 32 + d];
            }
            __syncthreads();
            int r0 = (tid >> 6) * 2;
            int k0 = (tid & 63) * 2;
            float s00 = 0, s01 = 0, s10 = 0, s11 = 0;
#pragma unroll
            for (int d = 0; d < 32; d++) {
                float qa = Qs[r0 * 32 + d], qb = Qs[(r0 + 1) * 32 + d];
                float ka = Ks[k0 * 33 + d], kb = Ks[(k0 + 1) * 33 + d];
                s00 += qa * ka; s01 += qa * kb;
                s10 += qb * ka; s11 += qb * kb;
            }
            int cb = kc * 128 + k0;
            Ps[r0 * 1024 + cb] = s00;       Ps[r0 * 1024 + cb + 1] = s01;
            Ps[(r0 + 1) * 1024 + cb] = s10; Ps[(r0 + 1) * 1024 + cb + 1] = s11;
        }
        __syncthreads();
        {
            int r = warp;
            float* row = Ps + r * 1024;
            float m = -1e30f;
            for (int i = lane; i < 1024; i += 32) m = fmaxf(m, row[i]);
#pragma unroll
            for (int o = 16; o > 0; o >>= 1) m = fmaxf(m, __shfl_xor_sync(0xffffffffu, m, o));
            float s = 0.f;
            for (int i = lane; i < 1024; i += 32) {
                float e = __expf(row[i] - m);
                row[i] = e;
                s += e;
            }
#pragma unroll
            for (int o = 16; o > 0; o >>= 1) s += __shfl_xor_sync(0xffffffffu, s, o);
            float inv = 1.f / s;
            float* arow = attnw + (qbase + r) * 1024;
            if (h == 0) {
                for (int i = lane; i < 1024; i += 32) {
                    float p = row[i] * inv; row[i] = p; arow[i] = 0.25f * p;
                }
            } else {
                for (int i = lane; i < 1024; i += 32) {
                    float p = row[i] * inv; row[i] = p; arow[i] += 0.25f * p;
                }
            }
        }
        {
            int r = tid >> 5, d = tid & 31;
            const float* prow = Ps + r * 1024;
            const float* vcol = g_v + h * 32 + d;
            float a0 = 0, a1 = 0, a2 = 0, a3 = 0;
#pragma unroll 2
            for (int k = 0; k < 1024; k += 4) {
                a0 += prow[k]     * vcol[(k)     * 128];
                a1 += prow[k + 1] * vcol[(k + 1) * 128];
                a2 += prow[k + 2] * vcol[(k + 2) * 128];
                a3 += prow[k + 3] * vcol[(k + 3) * 128];
            }
            g_ctx[(qbase + r) * 128 + h * 32 + d] = a0 + a1 + a2 + a3;
        }
        __syncthreads();
    }
}

// ---------------- out projection ---------------------------------------------
__global__ __launch_bounds__(128) void outproj_kernel(const float* __restrict__ W,
                                                      const float* __restrict__ b) {
    __shared__ float xs[8 * 128];
    int rb = blockIdx.x * 8;
    for (int i = threadIdx.x; i < 1024; i += 128) xs[i] = g_ctx[rb * 128 + i];
    __syncthreads();
    int j = threadIdx.x;
    const float4* w4 = (const float4*)(W + j * 128);
    const float4* xs4 = (const float4*)xs;
    float acc[8] = {0, 0, 0, 0, 0, 0, 0, 0};
#pragma unroll 8
    for (int i4 = 0; i4 < 32; i4++) {
        float4 w = w4[i4];
#pragma unroll
        for (int r = 0; r < 8; r++) {
            float4 xv = xs4[r * 32 + i4];
            acc[r] += w.x * xv.x + w.y * xv.y + w.z * xv.z + w.w * xv.w;
        }
    }
    float bj = b[j];
#pragma unroll
    for (int r = 0; r < 8; r++) g_att[(rb + r) * 128 + j] = acc[r] + bj;
}

// ---------------- t1 = task @ W1[:, :128]^T ; n1 = attended @ W1[:, 128:]^T --
__global__ __launch_bounds__(256) void t1n1_kernel(const float* __restrict__ task,
                                                   const float* __restrict__ W1) {
    __shared__ float xs[8 * 128];
    int half = blockIdx.x >> 7;
    int rb = (blockIdx.x & 127) * 8;
    const float* src = half ? g_att : task;
    for (int i = threadIdx.x; i < 1024; i += 256) xs[i] = src[rb * 128 + i];
    __syncthreads();
    int j = threadIdx.x;
    const float4* w4 = (const float4*)(W1 + j * 256 + half * 128);
    const float4* xs4 = (const float4*)xs;
    float acc[8] = {0, 0, 0, 0, 0, 0, 0, 0};
#pragma unroll 8
    for (int i4 = 0; i4 < 32; i4++) {
        float4 w = w4[i4];
#pragma unroll
        for (int r = 0; r < 8; r++) {
            float4 xv = xs4[r * 32 + i4];
            acc[r] += w.x * xv.x + w.y * xv.y + w.z * xv.z + w.w * xv.w;
        }
    }
    float* dst = half ? g_n1 : g_t1;
#pragma unroll
    for (int r = 0; r < 8; r++) dst[(rb + r) * 256 + j] = acc[r];
}

// ---------------- coordination head (tiny) -----------------------------------
__global__ __launch_bounds__(256) void coord_kernel(const float* __restrict__ Wc1,
                                                    const float* __restrict__ bc1,
                                                    const float* __restrict__ Wc2,
                                                    const float* __restrict__ bc2,
                                                    float* __restrict__ outc) {
    __shared__ float gs[128];
    __shared__ float hid[256];
    int tid = threadIdx.x;
    if (tid < 128) {
        float a0 = 0, a1 = 0, a2 = 0, a3 = 0;
        for (int i = 0; i < 1024; i += 4) {
            a0 += g_att[(i)     * 128 + tid];
            a1 += g_att[(i + 1) * 128 + tid];
            a2 += g_att[(i + 2) * 128 + tid];
            a3 += g_att[(i + 3) * 128 + tid];
        }
        gs[tid] = (a0 + a1 + a2 + a3) * (1.0f / 1024.0f);
    }
    __syncthreads();
    {
        const float* w = Wc1 + tid * 128;
        float acc = 0;
#pragma unroll 8
        for (int c = 0; c < 128; c++) acc += gs[c] * w[c];
        hid[tid] = fmaxf(acc + bc1[tid], 0.f);
    }
    __syncthreads();
    if (tid < 32) {
        const float* w = Wc2 + tid * 256;
        float acc = 0;
#pragma unroll 8
        for (int c = 0; c < 256; c++) acc += hid[c] * w[c];
        outc[tid] = acc + bc2[tid];
    }
}

// ============================================================================
// matching scores: 68.7 GFLOP pairwise MLP, bf16 mma.sync (m16n8k16),
// software-pipelined: double-buffered h1; next-tile gmem prefetch (pinned
// asm LDG) issues BEFORE the MMA loop so global latency hides under MMA.
// Block tile: 128 pairs (16t x 8n) x 128 kout, K=256. 8 warps as 4m x 2n.
// ============================================================================
#define MSTRIDE 264
#define MATCH_SMEM_BYTES (3 * 128 * MSTRIDE * 2 + (128 + 128 + 256) * 4)

__device__ __forceinline__ uint32_t packbf(float lo, float hi) {
    uint32_t r;
    asm("cvt.rn.bf16x2.f32 %0, %1, %2;" : "=r"(r) : "f"(hi), "f"(lo));
    return r;
}

// pack prefetched registers -> bf16 smem tile rows [warp*16 .. warp*16+15]
__device__ __forceinline__ void pack_tile(__nv_bfloat16* dst, int warp, int lane,
                                          const float4 tA[2][2],
                                          const float4 nA[8][2],
                                          const float* b1r) {
    int c0 = lane * 8;
#pragma unroll
    for (int h = 0; h < 2; h++) {
        float4 T0 = tA[h][0], T1 = tA[h][1];
#pragma unroll
        for (int n = 0; n < 8; n++) {
            float4 N0 = nA[n][0], N1 = nA[n][1];
            uint4 pk;
            pk.x = packbf(fmaxf(T0.x + N0.x + b1r[0], 0.f),
                          fmaxf(T0.y + N0.y + b1r[1], 0.f));
            pk.y = packbf(fmaxf(T0.z + N0.z + b1r[2], 0.f),
                          fmaxf(T0.w + N0.w + b1r[3], 0.f));
            pk.z = packbf(fmaxf(T1.x + N1.x + b1r[4], 0.f),
                          fmaxf(T1.y + N1.y + b1r[5], 0.f));
            pk.w = packbf(fmaxf(T1.z + N1.z + b1r[6], 0.f),
                          fmaxf(T1.w + N1.w + b1r[7], 0.f));
            *(uint4*)(dst + (warp * 16 + h * 8 + n) * MSTRIDE + c0) = pk;
        }
    }
}

#define LDG128(dst, ptr)                                                        \
    asm volatile("ld.global.nc.v4.f32 {%0,%1,%2,%3}, [%4];"                     \
                 : "=f"((dst).x), "=f"((dst).y), "=f"((dst).z), "=f"((dst).w)   \
                 : "l"(ptr))

__device__ __forceinline__ void load_tile(int tbase, int nbase, int warp,
                                          int lane, float4 tA[2][2],
                                          float4 nA[8][2]) {
    int c0 = lane * 8;
#pragma unroll
    for (int h = 0; h < 2; h++) {
        const float4* p = (const float4*)(g_t1 + (tbase + 2 * warp + h) * 256 + c0);
        LDG128(tA[h][0], p);
        LDG128(tA[h][1], p + 1);
    }
#pragma unroll
    for (int n = 0; n < 8; n++) {
        const float4* p = (const float4*)(g_n1 + (nbase + n) * 256 + c0);
        LDG128(nA[n][0], p);
        LDG128(nA[n][1], p + 1);
    }
}

__global__ __launch_bounds__(256, 1) void matching_kernel(
    const float* __restrict__ W2, const float* __restrict__ b2,
    const float* __restrict__ W3, const float* __restrict__ b1,
    const float* __restrict__ b3p, float* __restrict__ out) {
    extern __shared__ char smraw[];
    __nv_bfloat16* W2s = (__nv_bfloat16*)smraw;                 // [128][264]
    __nv_bfloat16* h1buf[2];
    h1buf[0] = W2s + 128 * MSTRIDE;                             // [128][264]
    h1buf[1] = h1buf[0] + 128 * MSTRIDE;                        // [128][264]
    float* b2s = (float*)(h1buf[1] + 128 * MSTRIDE);            // [128]
    float* W3s = b2s + 128;                                     // [128]
    float* red = W3s + 128;                                     // [128][2]

    int tid = threadIdx.x, lane = tid & 31, warp = tid >> 5;

    // W2 (fp32 -> bf16) resident in smem; biases
    for (int i = tid; i < 128 * 256; i += 256) {
        int r = i >> 8, c = i & 255;
        W2s[r * MSTRIDE + c] = __float2bfloat16_rn(W2[i]);
    }
    if (tid < 128) { b2s[tid] = b2[tid]; W3s[tid] = W3[tid]; }
    float b3v = b3p[0];
    float b1r[8];
#pragma unroll
    for (int j = 0; j < 8; j++) b1r[j] = b1[lane * 8 + j];

    // warp tiling: 4(m) x 2(n); warp tile 32 pairs x 64 kout
    int m0w = (warp >> 1) * 32;
    int n0w = (warp & 1) * 64;
    int gid = lane >> 2, tig = lane & 3;

    uint32_t w2_base = (uint32_t)__cvta_generic_to_shared(W2s);
    uint32_t h1_base[2] = {(uint32_t)__cvta_generic_to_shared(h1buf[0]),
                           (uint32_t)__cvta_generic_to_shared(h1buf[1])};
    uint32_t aOff[2];
#pragma unroll
    for (int mt = 0; mt < 2; mt++)
        aOff[mt] = (uint32_t)(((m0w + mt * 16 + (lane & 15)) * MSTRIDE +
                               ((lane >> 4) * 8)) * 2);
    int rowB = (lane & 7) + (((lane >> 4) & 1) << 3);
    int koffB = ((lane >> 3) & 1) * 8;
    uint32_t bAddr[4];
#pragma unroll
    for (int j = 0; j < 4; j++)
        bAddr[j] = w2_base + (uint32_t)(((n0w + j * 16 + rowB) * MSTRIDE + koffB) * 2);

    // prologue: build tile0 into buffer 0
    {
        int tile0 = blockIdx.x;
        float4 tA[2][2], nA[8][2];
        load_tile((tile0 >> 7) * 16, (tile0 & 127) * 8, warp, lane, tA, nA);
        pack_tile(h1buf[0], warp, lane, tA, nA, b1r);
    }
    __syncthreads();

    int it = 0;
    for (int tile = blockIdx.x; tile < 8192; tile += gridDim.x, it++) {
        int cur = it & 1;
        int tbase = (tile >> 7) * 16, nbase = (tile & 127) * 8;
        int ntile = tile + gridDim.x;

        // 1) prefetch next tile's operands (LDG latency hides under MMA loop)
        float4 tA[2][2], nA[8][2];
        if (ntile < 8192)
            load_tile((ntile >> 7) * 16, (ntile & 127) * 8, warp, lane, tA, nA);

        // 2) MMA loop on current buffer
        float acc[2][8][4];
#pragma unroll
        for (int mt = 0; mt < 2; mt++)
#pragma unroll
            for (int nt = 0; nt < 8; nt++)
#pragma unroll
                for (int i = 0; i < 4; i++) acc[mt][nt][i] = 0.f;

#pragma unroll 4
        for (int ks = 0; ks < 16; ks++) {
            uint32_t cb = ks * 32;
            uint32_t a[2][4], bq[4][4];
#pragma unroll
            for (int mt = 0; mt < 2; mt++)
                asm volatile(
                    "ldmatrix.sync.aligned.m8n8.x4.shared.b16 {%0,%1,%2,%3}, [%4];"
                    : "=r"(a[mt][0]), "=r"(a[mt][1]), "=r"(a[mt][2]), "=r"(a[mt][3])
                    : "r"(h1_base[cur] + aOff[mt] + cb));
#pragma unroll
            for (int j = 0; j < 4; j++)
                asm volatile(
                    "ldmatrix.sync.aligned.m8n8.x4.shared.b16 {%0,%1,%2,%3}, [%4];"
                    : "=r"(bq[j][0]), "=r"(bq[j][1]), "=r"(bq[j][2]), "=r"(bq[j][3])
                    : "r"(bAddr[j] + cb));
#pragma unroll
            for (int mt = 0; mt < 2; mt++)
#pragma unroll
                for (int j = 0; j < 4; j++) {
                    asm volatile(
                        "mma.sync.aligned.m16n8k16.row.col.f32.bf16.bf16.f32 "
                        "{%0,%1,%2,%3}, {%4,%5,%6,%7}, {%8,%9}, {%0,%1,%2,%3};"
                        : "+f"(acc[mt][2 * j][0]), "+f"(acc[mt][2 * j][1]),
                          "+f"(acc[mt][2 * j][2]), "+f"(acc[mt][2 * j][3])
                        : "r"(a[mt][0]), "r"(a[mt][1]), "r"(a[mt][2]), "r"(a[mt][3]),
                          "r"(bq[j][0]), "r"(bq[j][1]));
                    asm volatile(
                        "mma.sync.aligned.m16n8k16.row.col.f32.bf16.bf16.f32 "
                        "{%0,%1,%2,%3}, {%4,%5,%6,%7}, {%8,%9}, {%0,%1,%2,%3};"
                        : "+f"(acc[mt][2 * j + 1][0]), "+f"(acc[mt][2 * j + 1][1]),
                          "+f"(acc[mt][2 * j + 1][2]), "+f"(acc[mt][2 * j + 1][3])
                        : "r"(a[mt][0]), "r"(a[mt][1]), "r"(a[mt][2]), "r"(a[mt][3]),
                          "r"(bq[j][2]), "r"(bq[j][3]));
                }
        }

        // 3) pack prefetched regs into the other buffer
        if (ntile < 8192) pack_tile(h1buf[cur ^ 1], warp, lane, tA, nA, b1r);

        // 4) fused epilogue: z = sum_k relu(C + b2[k]) * W3[k]
        float part[2][2] = {{0, 0}, {0, 0}};
#pragma unroll
        for (int mt = 0; mt < 2; mt++)
#pragma unroll
            for (int nt = 0; nt < 8; nt++) {
                int cb = n0w + nt * 8 + tig * 2;
                float w3a = W3s[cb], w3b = W3s[cb + 1];
                float ba = b2s[cb], bb = b2s[cb + 1];
                part[mt][0] += fmaxf(acc[mt][nt][0] + ba, 0.f) * w3a +
                               fmaxf(acc[mt][nt][1] + bb, 0.f) * w3b;
                part[mt][1] += fmaxf(acc[mt][nt][2] + ba, 0.f) * w3a +
                               fmaxf(acc[mt][nt][3] + bb, 0.f) * w3b;
            }
#pragma unroll
        for (int mt = 0; mt < 2; mt++)
#pragma unroll
            for (int hh = 0; hh < 2; hh++) {
                float v = part[mt][hh];
                v += __shfl_xor_sync(0xffffffffu, v, 1);
                v += __shfl_xor_sync(0xffffffffu, v, 2);
                part[mt][hh] = v;
            }
        if (tig == 0) {
            int half = warp & 1;
#pragma unroll
            for (int mt = 0; mt < 2; mt++) {
                int r0 = m0w + mt * 16 + gid;
                red[r0 * 2 + half] = part[mt][0];
                red[(r0 + 8) * 2 + half] = part[mt][1];
            }
        }
        __syncthreads();  // red + next h1 buffer complete
        if (tid < 128) {
            float z = red[tid * 2] + red[tid * 2 + 1] + b3v;
            float s = 1.f / (1.f + __expf(-z));
            int t = tbase + (tid >> 3), n = nbase + (tid & 7);
            out[t * 1024 + n] = s;
        }
        __syncthreads();  // red consumed before next tile overwrites
    }
}

// ---------------- launch ------------------------------------------------------
extern "C" void kernel_launch(void* const* d_in, const int* in_sizes, int n_in,
                              void* d_out, int out_size) {
    const float* node_states = (const float*)d_in[0];
    const float* task_features = (const float*)d_in[1];
    const float* in_proj_w = (const float*)d_in[2];
    const float* in_proj_b = (const float*)d_in[3];
    const float* out_w = (const float*)d_in[4];
    const float* out_b = (const float*)d_in[5];
    const float* W1 = (const float*)d_in[6];
    const float* b1 = (const float*)d_in[7];
    const float* W2 = (const float*)d_in[8];
    const float* b2 = (const float*)d_in[9];
    const float* W3 = (const float*)d_in[10];
    const float* b3 = (const float*)d_in[11];
    const float* Wc1 = (const float*)d_in[12];
    const float* bc1 = (const float*)d_in[13];
    const float* Wc2 = (const float*)d_in[14];
    const float* bc2 = (const float*)d_in[15];

    float* out = (float*)d_out;
    float* matching = out;                       // [1024*1024]
    float* coord = out + 1024 * 1024;            // [32]
    float* attnw = out + 1024 * 1024 + 32;       // [1024*1024]

    cudaFuncSetAttribute((const void*)attn_kernel,
                         cudaFuncAttributeMaxDynamicSharedMemorySize, ATTN_SMEM_BYTES);
    cudaFuncSetAttribute((const void*)matching_kernel,
                         cudaFuncAttributeMaxDynamicSharedMemorySize, MATCH_SMEM_BYTES);

    qkv_kernel<<<128, 384>>>(node_states, in_proj_w, in_proj_b);
    attn_kernel<<<128, 256, ATTN_SMEM_BYTES>>>(attnw);
    outproj_kernel<<<128, 128>>>(out_w, out_b);
    t1n1_kernel<<<256, 256>>>(task_features, W1);
    coord_kernel<<<1, 256>>>(Wc1, bc1, Wc2, bc2, coord);
    matching_kernel<<<148, 256, MATCH_SMEM_BYTES>>>(W2, b2, W3, b1, b3, matching);
}

// round 12
// speedup vs baseline: 2.9343x; 1.2299x over previous
#include <cuda_runtime.h>
#include <cuda_bf16.h>
#include <cstdint>

// ---------------- scratch (no allocation allowed -> __device__ globals) -----
__device__ float g_q[1024 * 128];
__device__ float g_k[1024 * 128];
__device__ float g_v[1024 * 128];
__device__ float g_ctx[1024 * 128];
__device__ float g_att[1024 * 128];
__device__ float g_t1[1024 * 256];
__device__ float g_n1[1024 * 256];

// ---------------- QKV projection: q/k/v = x @ Wqkv^T + b --------------------
__global__ __launch_bounds__(384) void qkv_kernel(const float* __restrict__ x,
                                                  const float* __restrict__ W,
                                                  const float* __restrict__ b) {
    __shared__ float xs[8 * 128];
    int rb = blockIdx.x * 8;
    for (int i = threadIdx.x; i < 1024; i += 384) xs[i] = x[rb * 128 + i];
    __syncthreads();
    int j = threadIdx.x;
    const float4* w4 = (const float4*)(W + j * 128);
    const float4* xs4 = (const float4*)xs;
    float acc[8] = {0, 0, 0, 0, 0, 0, 0, 0};
#pragma unroll 8
    for (int i4 = 0; i4 < 32; i4++) {
        float4 w = w4[i4];
#pragma unroll
        for (int r = 0; r < 8; r++) {
            float4 xv = xs4[r * 32 + i4];
            acc[r] += w.x * xv.x + w.y * xv.y + w.z * xv.z + w.w * xv.w;
        }
    }
    float bj = b[j];
    float* dst;
    int col;
    if (j < 128) { dst = g_q; col = j; }
    else if (j < 256) { dst = g_k; col = j - 128; }
    else { dst = g_v; col = j - 256; }
#pragma unroll
    for (int r = 0; r < 8; r++) dst[(rb + r) * 128 + col] = acc[r] + bj;
}

// ---------------- attention (fp32; attn_w is an output) ----------------------
// Phase 1 per head: scores (conflict-free LDS) + softmax, probs kept in smem.
// Then: single-pass head-averaged attn_w write.
// Phase 2: ctx as chunked smem GEMM; each thread owns a float4 of output.
#define HSTRIDE 8200
#define ATTN_SMEM_BYTES ((4 * HSTRIDE + 128 * 132 + 256) * 4)
__global__ __launch_bounds__(256) void attn_kernel(float* __restrict__ attnw) {
    extern __shared__ float sm[];
    float* Ps4 = sm;                    // 4 heads x [8][1024], head stride 8200
    float* Vs = sm + 4 * HSTRIDE;       // [128][132]; doubles as Ks [128][33]
    float* Qs = Vs + 128 * 132;         // [8][32]
    float* Ks = Vs;
    int tid = threadIdx.x, lane = tid & 31, warp = tid >> 5;
    int qbase = blockIdx.x * 8;

    for (int h = 0; h < 4; h++) {
        float* Psh = Ps4 + h * HSTRIDE;
        __syncthreads();  // protect Qs/Ks reuse from previous head
        {
            int r = tid >> 5, d = tid & 31;
            Qs[tid] = g_q[(qbase + r) * 128 + h * 32 + d] * 0.17677669529663687f;
        }
        for (int kc = 0; kc < 8; kc++) {
            __syncthreads();
            for (int i = tid; i < 4096; i += 256) {
                int kk = i >> 5, d = i & 31;
                Ks[kk * 33 + d] = g_k[(kc * 128 + kk) * 128 + h * 32 + d];
            }
            __syncthreads();
            int r0 = (tid >> 6) * 2;
            int k0 = tid & 63;  // keys k0 and k0+64: conflict-free (stride 33)
            float s00 = 0, s01 = 0, s10 = 0, s11 = 0;
#pragma unroll
            for (int d = 0; d < 32; d++) {
                float qa = Qs[r0 * 32 + d], qb = Qs[(r0 + 1) * 32 + d];
                float ka = Ks[k0 * 33 + d], kb = Ks[(k0 + 64) * 33 + d];
                s00 += qa * ka; s01 += qa * kb;
                s10 += qb * ka; s11 += qb * kb;
            }
            int cb = kc * 128;
            Psh[r0 * 1024 + cb + k0] = s00;
            Psh[r0 * 1024 + cb + k0 + 64] = s01;
            Psh[(r0 + 1) * 1024 + cb + k0] = s10;
            Psh[(r0 + 1) * 1024 + cb + k0 + 64] = s11;
        }
        __syncthreads();
        {   // softmax: warp w owns row w; probs stay in Psh
            float* row = Psh + warp * 1024;
            float m = -1e30f;
            for (int i = lane; i < 1024; i += 32) m = fmaxf(m, row[i]);
#pragma unroll
            for (int o = 16; o > 0; o >>= 1) m = fmaxf(m, __shfl_xor_sync(0xffffffffu, m, o));
            float s = 0.f;
            for (int i = lane; i < 1024; i += 32) {
                float e = __expf(row[i] - m);
                row[i] = e;
                s += e;
            }
#pragma unroll
            for (int o = 16; o > 0; o >>= 1) s += __shfl_xor_sync(0xffffffffu, s, o);
            float inv = 1.f / s;
            for (int i = lane; i < 1024; i += 32) row[i] *= inv;
        }
    }
    __syncthreads();  // all heads' probs ready; Ks region now free

    // single-pass attn_w = mean over heads
    {
        float* arow = attnw + (qbase + warp) * 1024;
        int rb = warp * 1024;
        for (int i = lane; i < 1024; i += 32) {
            float s = Ps4[rb + i] + Ps4[HSTRIDE + rb + i] +
                      Ps4[2 * HSTRIDE + rb + i] + Ps4[3 * HSTRIDE + rb + i];
            arow[i] = 0.25f * s;
        }
    }

    // phase 2: ctx[r, d0..d0+3] = sum_k p_head[r,k] * V[k, d0..d0+3]
    int r = tid >> 5, dq = tid & 31, head = dq >> 3;
    const float* prowbase = Ps4 + head * HSTRIDE + r * 1024;
    float4 acc = {0.f, 0.f, 0.f, 0.f};
    for (int kc = 0; kc < 8; kc++) {
        __syncthreads();  // prev chunk consumption done
        for (int i = tid; i < 4096; i += 256) {
            int kk = i >> 5, c4 = i & 31;
            ((float4*)(Vs + kk * 132))[c4] =
                *(const float4*)(g_v + (kc * 128 + kk) * 128 + c4 * 4);
        }
        __syncthreads();
        const float* prow = prowbase + kc * 128;
#pragma unroll 4
        for (int k = 0; k < 128; k++) {
            float p = prow[k];
            float4 v = ((const float4*)(Vs + k * 132))[dq];
            acc.x += p * v.x; acc.y += p * v.y;
            acc.z += p * v.z; acc.w += p * v.w;
        }
    }
    *(float4*)(g_ctx + (qbase + r) * 128 + dq * 4) = acc;
}

// ---------------- out projection ---------------------------------------------
__global__ __launch_bounds__(128) void outproj_kernel(const float* __restrict__ W,
                                                      const float* __restrict__ b) {
    __shared__ float xs[8 * 128];
    int rb = blockIdx.x * 8;
    for (int i = threadIdx.x; i < 1024; i += 128) xs[i] = g_ctx[rb * 128 + i];
    __syncthreads();
    int j = threadIdx.x;
    const float4* w4 = (const float4*)(W + j * 128);
    const float4* xs4 = (const float4*)xs;
    float acc[8] = {0, 0, 0, 0, 0, 0, 0, 0};
#pragma unroll 8
    for (int i4 = 0; i4 < 32; i4++) {
        float4 w = w4[i4];
#pragma unroll
        for (int r = 0; r < 8; r++) {
            float4 xv = xs4[r * 32 + i4];
            acc[r] += w.x * xv.x + w.y * xv.y + w.z * xv.z + w.w * xv.w;
        }
    }
    float bj = b[j];
#pragma unroll
    for (int r = 0; r < 8; r++) g_att[(rb + r) * 128 + j] = acc[r] + bj;
}

// ---------------- t1 = task @ W1[:, :128]^T ; n1 = attended @ W1[:, 128:]^T --
__global__ __launch_bounds__(256) void t1n1_kernel(const float* __restrict__ task,
                                                   const float* __restrict__ W1) {
    __shared__ float xs[8 * 128];
    int half = blockIdx.x >> 7;
    int rb = (blockIdx.x & 127) * 8;
    const float* src = half ? g_att : task;
    for (int i = threadIdx.x; i < 1024; i += 256) xs[i] = src[rb * 128 + i];
    __syncthreads();
    int j = threadIdx.x;
    const float4* w4 = (const float4*)(W1 + j * 256 + half * 128);
    const float4* xs4 = (const float4*)xs;
    float acc[8] = {0, 0, 0, 0, 0, 0, 0, 0};
#pragma unroll 8
    for (int i4 = 0; i4 < 32; i4++) {
        float4 w = w4[i4];
#pragma unroll
        for (int r = 0; r < 8; r++) {
            float4 xv = xs4[r * 32 + i4];
            acc[r] += w.x * xv.x + w.y * xv.y + w.z * xv.z + w.w * xv.w;
        }
    }
    float* dst = half ? g_n1 : g_t1;
#pragma unroll
    for (int r = 0; r < 8; r++) dst[(rb + r) * 256 + j] = acc[r];
}

// ---------------- coordination head (tiny) -----------------------------------
__global__ __launch_bounds__(256) void coord_kernel(const float* __restrict__ Wc1,
                                                    const float* __restrict__ bc1,
                                                    const float* __restrict__ Wc2,
                                                    const float* __restrict__ bc2,
                                                    float* __restrict__ outc) {
    __shared__ float gs[128];
    __shared__ float hid[256];
    int tid = threadIdx.x;
    if (tid < 128) {
        float a0 = 0, a1 = 0, a2 = 0, a3 = 0;
        for (int i = 0; i < 1024; i += 4) {
            a0 += g_att[(i)     * 128 + tid];
            a1 += g_att[(i + 1) * 128 + tid];
            a2 += g_att[(i + 2) * 128 + tid];
            a3 += g_att[(i + 3) * 128 + tid];
        }
        gs[tid] = (a0 + a1 + a2 + a3) * (1.0f / 1024.0f);
    }
    __syncthreads();
    {
        const float* w = Wc1 + tid * 128;
        float acc = 0;
#pragma unroll 8
        for (int c = 0; c < 128; c++) acc += gs[c] * w[c];
        hid[tid] = fmaxf(acc + bc1[tid], 0.f);
    }
    __syncthreads();
    if (tid < 32) {
        const float* w = Wc2 + tid * 256;
        float acc = 0;
#pragma unroll 8
        for (int c = 0; c < 256; c++) acc += hid[c] * w[c];
        outc[tid] = acc + bc2[tid];
    }
}

// ============================================================================
// matching scores: 68.7 GFLOP pairwise MLP, bf16 mma.sync (m16n8k16).
// Pipelined: prefetch next tile (LDG) before MMA loop; pack of next tile's h1
// interleaved INTO MMA k-steps 8..15 (FMA pipe fills tensor-pipe shadow);
// single-sync epilogue with parity-double-buffered reduction array.
// ============================================================================
#define MSTRIDE 264
#define MATCH_SMEM_BYTES (3 * 128 * MSTRIDE * 2 + (128 + 128 + 512) * 4)

__device__ __forceinline__ uint32_t packbf(float lo, float hi) {
    uint32_t r;
    asm("cvt.rn.bf16x2.f32 %0, %1, %2;" : "=r"(r) : "f"(hi), "f"(lo));
    return r;
}

#define LDG128(dst, ptr)                                                        \
    asm volatile("ld.global.nc.v4.f32 {%0,%1,%2,%3}, [%4];"                     \
                 : "=f"((dst).x), "=f"((dst).y), "=f"((dst).z), "=f"((dst).w)   \
                 : "l"(ptr))

__device__ __forceinline__ void load_tile(int tbase, int nbase, int warp,
                                          int lane, float4 tA[2][2],
                                          float4 nA[8][2]) {
    int c0 = lane * 8;
#pragma unroll
    for (int h = 0; h < 2; h++) {
        const float4* p = (const float4*)(g_t1 + (tbase + 2 * warp + h) * 256 + c0);
        LDG128(tA[h][0], p);
        LDG128(tA[h][1], p + 1);
    }
#pragma unroll
    for (int n = 0; n < 8; n++) {
        const float4* p = (const float4*)(g_n1 + (nbase + n) * 256 + c0);
        LDG128(nA[n][0], p);
        LDG128(nA[n][1], p + 1);
    }
}

// pack one n-row pair (rows warp*16+n and warp*16+8+n) of the next h1 tile
__device__ __forceinline__ void pack_rows(__nv_bfloat16* dst, int warp, int lane,
                                          const float4 tA[2][2], float4 N0,
                                          float4 N1, const float* b1r, int n) {
    int c0 = lane * 8;
#pragma unroll
    for (int h = 0; h < 2; h++) {
        float4 T0 = tA[h][0], T1 = tA[h][1];
        uint4 pk;
        pk.x = packbf(fmaxf(T0.x + N0.x + b1r[0], 0.f),
                      fmaxf(T0.y + N0.y + b1r[1], 0.f));
        pk.y = packbf(fmaxf(T0.z + N0.z + b1r[2], 0.f),
                      fmaxf(T0.w + N0.w + b1r[3], 0.f));
        pk.z = packbf(fmaxf(T1.x + N1.x + b1r[4], 0.f),
                      fmaxf(T1.y + N1.y + b1r[5], 0.f));
        pk.w = packbf(fmaxf(T1.z + N1.z + b1r[6], 0.f),
                      fmaxf(T1.w + N1.w + b1r[7], 0.f));
        *(uint4*)(dst + (warp * 16 + h * 8 + n) * MSTRIDE + c0) = pk;
    }
}

__global__ __launch_bounds__(256, 1) void matching_kernel(
    const float* __restrict__ W2, const float* __restrict__ b2,
    const float* __restrict__ W3, const float* __restrict__ b1,
    const float* __restrict__ b3p, float* __restrict__ out) {
    extern __shared__ char smraw[];
    __nv_bfloat16* W2s = (__nv_bfloat16*)smraw;                 // [128][264]
    __nv_bfloat16* h1buf[2];
    h1buf[0] = W2s + 128 * MSTRIDE;
    h1buf[1] = h1buf[0] + 128 * MSTRIDE;
    float* b2s = (float*)(h1buf[1] + 128 * MSTRIDE);            // [128]
    float* W3s = b2s + 128;                                     // [128]
    float* red = W3s + 128;                                     // [2][128][2]

    int tid = threadIdx.x, lane = tid & 31, warp = tid >> 5;

    for (int i = tid; i < 128 * 256; i += 256) {
        int r = i >> 8, c = i & 255;
        W2s[r * MSTRIDE + c] = __float2bfloat16_rn(W2[i]);
    }
    if (tid < 128) { b2s[tid] = b2[tid]; W3s[tid] = W3[tid]; }
    float b3v = b3p[0];
    float b1r[8];
#pragma unroll
    for (int j = 0; j < 8; j++) b1r[j] = b1[lane * 8 + j];

    int m0w = (warp >> 1) * 32;
    int n0w = (warp & 1) * 64;
    int gid = lane >> 2, tig = lane & 3;

    uint32_t w2_base = (uint32_t)__cvta_generic_to_shared(W2s);
    uint32_t h1_base[2] = {(uint32_t)__cvta_generic_to_shared(h1buf[0]),
                           (uint32_t)__cvta_generic_to_shared(h1buf[1])};
    uint32_t aOff[2];
#pragma unroll
    for (int mt = 0; mt < 2; mt++)
        aOff[mt] = (uint32_t)(((m0w + mt * 16 + (lane & 15)) * MSTRIDE +
                               ((lane >> 4) * 8)) * 2);
    int rowB = (lane & 7) + (((lane >> 4) & 1) << 3);
    int koffB = ((lane >> 3) & 1) * 8;
    uint32_t bAddr[4];
#pragma unroll
    for (int j = 0; j < 4; j++)
        bAddr[j] = w2_base + (uint32_t)(((n0w + j * 16 + rowB) * MSTRIDE + koffB) * 2);

    // prologue: build tile0 into buffer 0
    {
        int tile0 = blockIdx.x;
        float4 tA[2][2], nA[8][2];
        load_tile((tile0 >> 7) * 16, (tile0 & 127) * 8, warp, lane, tA, nA);
#pragma unroll
        for (int n = 0; n < 8; n++)
            pack_rows(h1buf[0], warp, lane, tA, nA[n][0], nA[n][1], b1r, n);
    }
    __syncthreads();

    int it = 0;
    for (int tile = blockIdx.x; tile < 8192; tile += gridDim.x, it++) {
        int cur = it & 1;
        int tbase = (tile >> 7) * 16, nbase = (tile & 127) * 8;
        int ntile = tile + gridDim.x;
        bool have_next = (ntile < 8192);

        // 1) prefetch next tile's operands (latency buried under MMA loop)
        float4 tA[2][2], nA[8][2];
        if (have_next)
            load_tile((ntile >> 7) * 16, (ntile & 127) * 8, warp, lane, tA, nA);

        // 2) MMA loop; pack of next tile interleaved into steps 8..15
        float acc[2][8][4];
#pragma unroll
        for (int mt = 0; mt < 2; mt++)
#pragma unroll
            for (int nt = 0; nt < 8; nt++)
#pragma unroll
                for (int i = 0; i < 4; i++) acc[mt][nt][i] = 0.f;

#pragma unroll
        for (int ks = 0; ks < 16; ks++) {
            uint32_t cb = ks * 32;
            uint32_t a[2][4], bq[4][4];
#pragma unroll
            for (int mt = 0; mt < 2; mt++)
                asm volatile(
                    "ldmatrix.sync.aligned.m8n8.x4.shared.b16 {%0,%1,%2,%3}, [%4];"
                    : "=r"(a[mt][0]), "=r"(a[mt][1]), "=r"(a[mt][2]), "=r"(a[mt][3])
                    : "r"(h1_base[cur] + aOff[mt] + cb));
#pragma unroll
            for (int j = 0; j < 4; j++)
                asm volatile(
                    "ldmatrix.sync.aligned.m8n8.x4.shared.b16 {%0,%1,%2,%3}, [%4];"
                    : "=r"(bq[j][0]), "=r"(bq[j][1]), "=r"(bq[j][2]), "=r"(bq[j][3])
                    : "r"(bAddr[j] + cb));
#pragma unroll
            for (int mt = 0; mt < 2; mt++)
#pragma unroll
                for (int j = 0; j < 4; j++) {
                    asm volatile(
                        "mma.sync.aligned.m16n8k16.row.col.f32.bf16.bf16.f32 "
                        "{%0,%1,%2,%3}, {%4,%5,%6,%7}, {%8,%9}, {%0,%1,%2,%3};"
                        : "+f"(acc[mt][2 * j][0]), "+f"(acc[mt][2 * j][1]),
                          "+f"(acc[mt][2 * j][2]), "+f"(acc[mt][2 * j][3])
                        : "r"(a[mt][0]), "r"(a[mt][1]), "r"(a[mt][2]), "r"(a[mt][3]),
                          "r"(bq[j][0]), "r"(bq[j][1]));
                    asm volatile(
                        "mma.sync.aligned.m16n8k16.row.col.f32.bf16.bf16.f32 "
                        "{%0,%1,%2,%3}, {%4,%5,%6,%7}, {%8,%9}, {%0,%1,%2,%3};"
                        : "+f"(acc[mt][2 * j + 1][0]), "+f"(acc[mt][2 * j + 1][1]),
                          "+f"(acc[mt][2 * j + 1][2]), "+f"(acc[mt][2 * j + 1][3])
                        : "r"(a[mt][0]), "r"(a[mt][1]), "r"(a[mt][2]), "r"(a[mt][3]),
                          "r"(bq[j][2]), "r"(bq[j][3]));
                }
            if (ks >= 8 && have_next)
                pack_rows(h1buf[cur ^ 1], warp, lane, tA, nA[ks - 8][0],
                          nA[ks - 8][1], b1r, ks - 8);
        }

        // 3) fused epilogue: z = sum_k relu(C + b2[k]) * W3[k]
        float part[2][2] = {{0, 0}, {0, 0}};
#pragma unroll
        for (int mt = 0; mt < 2; mt++)
#pragma unroll
            for (int nt = 0; nt < 8; nt++) {
                int cb = n0w + nt * 8 + tig * 2;
                float w3a = W3s[cb], w3b = W3s[cb + 1];
                float ba = b2s[cb], bb = b2s[cb + 1];
                part[mt][0] += fmaxf(acc[mt][nt][0] + ba, 0.f) * w3a +
                               fmaxf(acc[mt][nt][1] + bb, 0.f) * w3b;
                part[mt][1] += fmaxf(acc[mt][nt][2] + ba, 0.f) * w3a +
                               fmaxf(acc[mt][nt][3] + bb, 0.f) * w3b;
            }
#pragma unroll
        for (int mt = 0; mt < 2; mt++)
#pragma unroll
            for (int hh = 0; hh < 2; hh++) {
                float v = part[mt][hh];
                v += __shfl_xor_sync(0xffffffffu, v, 1);
                v += __shfl_xor_sync(0xffffffffu, v, 2);
                part[mt][hh] = v;
            }
        float* redc = red + cur * 256;
        if (tig == 0) {
            int half = warp & 1;
#pragma unroll
            for (int mt = 0; mt < 2; mt++) {
                int r0 = m0w + mt * 16 + gid;
                redc[r0 * 2 + half] = part[mt][0];
                redc[(r0 + 8) * 2 + half] = part[mt][1];
            }
        }
        __syncthreads();  // red ready AND next h1 buffer fully packed
        if (tid < 128) {
            float z = redc[tid * 2] + redc[tid * 2 + 1] + b3v;
            float s = 1.f / (1.f + __expf(-z));
            int t = tbase + (tid >> 3), n = nbase + (tid & 7);
            out[t * 1024 + n] = s;
        }
        // no second sync: next tile writes red[cur^1] / h1buf[cur] only
    }
}

// ---------------- launch ------------------------------------------------------
extern "C" void kernel_launch(void* const* d_in, const int* in_sizes, int n_in,
                              void* d_out, int out_size) {
    const float* node_states = (const float*)d_in[0];
    const float* task_features = (const float*)d_in[1];
    const float* in_proj_w = (const float*)d_in[2];
    const float* in_proj_b = (const float*)d_in[3];
    const float* out_w = (const float*)d_in[4];
    const float* out_b = (const float*)d_in[5];
    const float* W1 = (const float*)d_in[6];
    const float* b1 = (const float*)d_in[7];
    const float* W2 = (const float*)d_in[8];
    const float* b2 = (const float*)d_in[9];
    const float* W3 = (const float*)d_in[10];
    const float* b3 = (const float*)d_in[11];
    const float* Wc1 = (const float*)d_in[12];
    const float* bc1 = (const float*)d_in[13];
    const float* Wc2 = (const float*)d_in[14];
    const float* bc2 = (const float*)d_in[15];

    float* out = (float*)d_out;
    float* matching = out;                       // [1024*1024]
    float* coord = out + 1024 * 1024;            // [32]
    float* attnw = out + 1024 * 1024 + 32;       // [1024*1024]

    cudaFuncSetAttribute((const void*)attn_kernel,
                         cudaFuncAttributeMaxDynamicSharedMemorySize, ATTN_SMEM_BYTES);
    cudaFuncSetAttribute((const void*)matching_kernel,
                         cudaFuncAttributeMaxDynamicSharedMemorySize, MATCH_SMEM_BYTES);

    qkv_kernel<<<128, 384>>>(node_states, in_proj_w, in_proj_b);
    attn_kernel<<<128, 256, ATTN_SMEM_BYTES>>>(attnw);
    outproj_kernel<<<128, 128>>>(out_w, out_b);
    t1n1_kernel<<<256, 256>>>(task_features, W1);
    coord_kernel<<<1, 256>>>(Wc1, bc1, Wc2, bc2, coord);
    matching_kernel<<<148, 256, MATCH_SMEM_BYTES>>>(W2, b2, W3, b1, b3, matching);
}